// round 3
// baseline (speedup 1.0000x reference)
// Resubmission: R1/R2 failed with "GB300 container failed twice" (broker
// infra, kernel never executed). Logic unchanged from R0; re-verified by hand.
#include <cuda_runtime.h>
#include <cstdint>

// Problem constants
#define BB 4
#define SS 2048
#define EE 1024
#define HH 16
#define PP 8
#define DD 64
#define NTOK (BB*SS)          // 8192
#define QSIZE (BB*HH*SS*DD)   // 8,388,608 floats per tensor (q, k, v)

// SqSoftplus constants
#define C_B 2.0480546988460353f
#define C_C 0.841470984807896f
#define C_A 0.45339765151640377f
#define C_NU 0.999999327348f   // log(2.71828)
#define C_EPS 1e-6f

// ---------------------------------------------------------------------------
// Scratch: Wsum1/Wsum2 (H*P*D = 8192 floats each)
// ---------------------------------------------------------------------------
__device__ float g_Wsum1[HH*PP*DD];
__device__ float g_Wsum2[HH*PP*DD];

// ---------------------------------------------------------------------------
// helpers
// ---------------------------------------------------------------------------
__device__ __forceinline__ float warp_sum(float v) {
#pragma unroll
    for (int o = 16; o; o >>= 1) v += __shfl_xor_sync(0xffffffffu, v, o);
    return v;
}

__device__ __forceinline__ float softplusf(float z) {
    float az = fabsf(z);
    float e  = __expf(-az);
    return fmaxf(z, 0.0f) + __logf(1.0f + e);
}

__device__ __forceinline__ float sqspf(float x) {
    float t1 = softplusf(C_B * x) * (1.0f / C_B);
    float t2 = softplusf(C_C * x) * (1.0f / C_C);
    float y  = (1.0f - C_A) * t1 + C_A * t2;
    return y * y;
}

// packed f32x2 helpers
__device__ __forceinline__ unsigned long long dup2(float v) {
    unsigned long long r;
    asm("mov.b64 %0, {%1, %1};" : "=l"(r) : "f"(v));
    return r;
}
__device__ __forceinline__ void fma2(unsigned long long& d,
                                     unsigned long long a,
                                     unsigned long long b) {
    asm("fma.rn.f32x2 %0, %1, %2, %0;" : "+l"(d) : "l"(a), "l"(b));
}
__device__ __forceinline__ float2 unpack2(unsigned long long v) {
    float2 r;
    asm("mov.b64 {%0, %1}, %2;" : "=f"(r.x), "=f"(r.y) : "l"(v));
    return r;
}

// ---------------------------------------------------------------------------
// Kernel 1: Wsum[h,p,o] = sum_j W[h,p,o,j]   (one warp per output element)
// ---------------------------------------------------------------------------
__global__ void wsum_kernel(const float* __restrict__ W1,
                            const float* __restrict__ W2) {
    int idx  = blockIdx.x * 8 + (threadIdx.x >> 5);   // 0..8191
    int lane = threadIdx.x & 31;
    const float* w1 = W1 + (size_t)idx * DD;
    const float* w2 = W2 + (size_t)idx * DD;
    float s1 = w1[lane] + w1[lane + 32];
    float s2 = w2[lane] + w2[lane + 32];
    s1 = warp_sum(s1);
    s2 = warp_sum(s2);
    if (lane == 0) {
        g_Wsum1[idx] = s1;
        g_Wsum2[idx] = s2;
    }
}

// ---------------------------------------------------------------------------
// Kernel 2: qk GEMM  qk[n,j] = sum_e x[n,e]*qk_w[j,e]
// 128x128 tile, BK=8, 256 threads, 8x8 per thread, f32x2 FMAs.
// Writes q (j<1024) and k (j>=1024) directly in (B,H,S,D) layout.
// ---------------------------------------------------------------------------
#define LDA 140   // 128 + 12 pad: breaks store bank conflicts, keeps 16B align

__global__ __launch_bounds__(256)
void qk_gemm_kernel(const float* __restrict__ A,   // x  [8192,1024]
                    const float* __restrict__ Bm,  // qk_w [2048,1024]
                    float* __restrict__ out) {
    __shared__ float As[8][LDA];
    __shared__ float Bs[8][LDA];

    int tid = threadIdx.x;
    int loadRow = tid >> 1;          // 0..127
    int loadCol = (tid & 1) << 2;    // 0 or 4

    const float* Aptr = A  + (size_t)(blockIdx.y * 128 + loadRow) * EE + loadCol;
    const float* Bptr = Bm + (size_t)(blockIdx.x * 128 + loadRow) * EE + loadCol;

    int tm = tid >> 4;   // 0..15 (row group)
    int tn = tid & 15;   // 0..15 (col group)

    unsigned long long acc[8][4];
#pragma unroll
    for (int i = 0; i < 8; ++i)
#pragma unroll
        for (int j = 0; j < 4; ++j) acc[i][j] = 0ull;

    for (int kt = 0; kt < EE / 8; ++kt) {
        float4 va = *(const float4*)Aptr;
        float4 vb = *(const float4*)Bptr;
        Aptr += 8; Bptr += 8;
        __syncthreads();
        As[loadCol + 0][loadRow] = va.x;
        As[loadCol + 1][loadRow] = va.y;
        As[loadCol + 2][loadRow] = va.z;
        As[loadCol + 3][loadRow] = va.w;
        Bs[loadCol + 0][loadRow] = vb.x;
        Bs[loadCol + 1][loadRow] = vb.y;
        Bs[loadCol + 2][loadRow] = vb.z;
        Bs[loadCol + 3][loadRow] = vb.w;
        __syncthreads();

#pragma unroll
        for (int k = 0; k < 8; ++k) {
            float4 a0 = *(const float4*)&As[k][tm * 8];
            float4 a1 = *(const float4*)&As[k][tm * 8 + 4];
            const unsigned long long* bq =
                (const unsigned long long*)&Bs[k][tn * 8];
            unsigned long long bv0 = bq[0], bv1 = bq[1],
                               bv2 = bq[2], bv3 = bq[3];
            float av[8] = {a0.x, a0.y, a0.z, a0.w, a1.x, a1.y, a1.z, a1.w};
#pragma unroll
            for (int i = 0; i < 8; ++i) {
                unsigned long long ad = dup2(av[i]);
                fma2(acc[i][0], ad, bv0);
                fma2(acc[i][1], ad, bv1);
                fma2(acc[i][2], ad, bv2);
                fma2(acc[i][3], ad, bv3);
            }
        }
    }

    // epilogue: scatter into q/k (B,H,S,D) layout
    int colBase = blockIdx.x * 128 + tn * 8;  // global j, 8 contiguous cols
    int inK   = (colBase >= EE) ? 1 : 0;
    int jc    = colBase & (EE - 1);
    int h     = jc >> 6;
    int dbase = jc & 63;
    size_t tensorOff = inK ? (size_t)QSIZE : 0;

#pragma unroll
    for (int i = 0; i < 8; ++i) {
        int r  = blockIdx.y * 128 + tm * 8 + i;  // token index n
        int b_ = r >> 11;
        int s_ = r & (SS - 1);
        float* op = out + tensorOff +
                    (((size_t)b_ * HH + h) * SS + s_) * DD + dbase;
        float2 p0 = unpack2(acc[i][0]);
        float2 p1 = unpack2(acc[i][1]);
        float2 p2 = unpack2(acc[i][2]);
        float2 p3 = unpack2(acc[i][3]);
        float4 w0 = make_float4(p0.x, p0.y, p1.x, p1.y);
        float4 w1 = make_float4(p2.x, p2.y, p3.x, p3.y);
        *(float4*)op       = w0;
        *(float4*)(op + 4) = w1;
    }
}

// ---------------------------------------------------------------------------
// Kernel 3: fused vector-hull. One warp per token (per head), lanes cover
// o = lane and o = lane+32. Head constants staged in SMEM.
// ---------------------------------------------------------------------------
#define TOKS_PER_WARP 4

__global__ __launch_bounds__(256)
void vhull_kernel(const float* __restrict__ x,
                  const float* __restrict__ b1,
                  const float* __restrict__ b2,
                  const float* __restrict__ gate_w,
                  const float* __restrict__ gate_b,
                  float* __restrict__ vout) {
    __shared__ float sW1[PP * DD];
    __shared__ float sB1[PP * DD];
    __shared__ float sW2[PP * DD];
    __shared__ float sB2[PP * DD];
    __shared__ float sGw[DD];

    int h = blockIdx.y;
    for (int i = threadIdx.x; i < PP * DD; i += 256) {
        sW1[i] = g_Wsum1[h * PP * DD + i];
        sB1[i] = b1[h * PP * DD + i];
        sW2[i] = g_Wsum2[h * PP * DD + i];
        sB2[i] = b2[h * PP * DD + i];
    }
    if (threadIdx.x < DD) sGw[threadIdx.x] = gate_w[h * DD + threadIdx.x];
    float gb = gate_b[h];
    __syncthreads();

    int warp = threadIdx.x >> 5;
    int lane = threadIdx.x & 31;
    int tokBase = (blockIdx.x * 8 + warp) * TOKS_PER_WARP;

    for (int t = 0; t < TOKS_PER_WARP; ++t) {
        int n = tokBase + t;
        const float* xp = x + (size_t)n * EE + h * DD;
        float xh0 = xp[lane];
        float xh1 = xp[lane + 32];

        // gate
        float dot = warp_sum(xh0 * sGw[lane] + xh1 * sGw[lane + 32]);
        float u = sqspf(dot + gb);
        float g = 1.0f - __expf(-u);
        float xg0 = xh0 * g;
        float xg1 = xh1 * g;

        float s  = warp_sum(xg0 + xg1);
        float q2 = warp_sum(xg0 * xg0 + xg1 * xg1);
        float tau = sqrtf(q2 * (1.0f / DD) + C_EPS + C_NU);
        float inv_tau = 1.0f / tau;

        // layer 1: t[p] = sum_o sqsp(s*Wsum1[p,o] + b1[p,o])
        float tp[PP];
#pragma unroll
        for (int p = 0; p < PP; ++p) {
            int i0 = p * DD + lane;
            float z0 = sqspf(fmaf(s, sW1[i0],      sB1[i0]));
            float z1 = sqspf(fmaf(s, sW1[i0 + 32], sB1[i0 + 32]));
            tp[p] = warp_sum(z0 + z1);
        }

        // layer 2 + logsumexp over p for this lane's two o values
        float vres[2];
#pragma unroll
        for (int oo = 0; oo < 2; ++oo) {
            int o = lane + oo * 32;
            float a[PP];
            float m = -3.4e38f;
#pragma unroll
            for (int p = 0; p < PP; ++p) {
                a[p] = sqspf(fmaf(tp[p], sW2[p * DD + o], sB2[p * DD + o]));
                m = fmaxf(m, a[p]);
            }
            float sume = 0.0f;
#pragma unroll
            for (int p = 0; p < PP; ++p)
                sume += __expf((a[p] - m) * tau);
            vres[oo] = m + __logf(sume) * inv_tau;
        }

        int b_ = n >> 11;
        int s_ = n & (SS - 1);
        float* op = vout + (((size_t)b_ * HH + h) * SS + s_) * DD;
        op[lane]      = vres[0];
        op[lane + 32] = vres[1];
    }
}

// ---------------------------------------------------------------------------
// launch
// ---------------------------------------------------------------------------
extern "C" void kernel_launch(void* const* d_in, const int* in_sizes, int n_in,
                              void* d_out, int out_size) {
    const float* x      = (const float*)d_in[0];
    const float* qk_w   = (const float*)d_in[1];
    const float* W1     = (const float*)d_in[2];
    const float* b1     = (const float*)d_in[3];
    const float* W2     = (const float*)d_in[4];
    const float* b2     = (const float*)d_in[5];
    const float* gate_w = (const float*)d_in[6];
    const float* gate_b = (const float*)d_in[7];
    float* out = (float*)d_out;

    // Wsum reduction: 8192 outputs, one warp each
    wsum_kernel<<<1024, 256>>>(W1, W2);

    // QK GEMM: grid (N/128, M/128) = (16, 64)
    dim3 ggrid(2048 / 128, NTOK / 128);
    qk_gemm_kernel<<<ggrid, 256>>>(x, qk_w, out);

    // V hull: grid (tokens/32, H) = (256, 16)
    dim3 vgrid(NTOK / (8 * TOKS_PER_WARP), HH);
    vhull_kernel<<<vgrid, 256>>>(x, b1, b2, gate_w, gate_b,
                                 out + 2 * (size_t)QSIZE);
}

// round 5
// speedup vs baseline: 1.8666x; 1.8666x over previous
// R5: tcgen05 unavailable (harness targets plain sm_100) -> mma.sync bf16
// 2-way-split HMMA GEMM + cp.async pipeline. wsum + vhull unchanged from R3.
#include <cuda_runtime.h>
#include <cuda_bf16.h>
#include <cstdint>

// Problem constants
#define BB 4
#define SS 2048
#define EE 1024
#define HH 16
#define PP 8
#define DD 64
#define NTOK (BB*SS)          // 8192
#define QSIZE (BB*HH*SS*DD)   // 8,388,608 floats per tensor (q, k, v)
#define NQK 2048              // rows of qk_w

// SqSoftplus constants
#define C_B 2.0480546988460353f
#define C_C 0.841470984807896f
#define C_A 0.45339765151640377f
#define C_NU 0.999999327348f   // log(2.71828)
#define C_EPS 1e-6f

// ---------------------------------------------------------------------------
// Scratch
// ---------------------------------------------------------------------------
__device__ float g_Wsum1[HH*PP*DD];
__device__ float g_Wsum2[HH*PP*DD];
__device__ __nv_bfloat16 g_xhi[(size_t)NTOK*EE];
__device__ __nv_bfloat16 g_xlo[(size_t)NTOK*EE];
__device__ __nv_bfloat16 g_whi[(size_t)NQK*EE];
__device__ __nv_bfloat16 g_wlo[(size_t)NQK*EE];

// ---------------------------------------------------------------------------
// helpers
// ---------------------------------------------------------------------------
__device__ __forceinline__ uint32_t smem_u32(const void* p) {
    uint32_t a;
    asm("{ .reg .u64 t; cvta.to.shared.u64 t, %1; cvt.u32.u64 %0, t; }"
        : "=r"(a) : "l"(p));
    return a;
}
__device__ __forceinline__ float warp_sum(float v) {
#pragma unroll
    for (int o = 16; o; o >>= 1) v += __shfl_xor_sync(0xffffffffu, v, o);
    return v;
}
__device__ __forceinline__ float softplusf(float z) {
    float az = fabsf(z);
    float e  = __expf(-az);
    return fmaxf(z, 0.0f) + __logf(1.0f + e);
}
__device__ __forceinline__ float sqspf(float x) {
    float t1 = softplusf(C_B * x) * (1.0f / C_B);
    float t2 = softplusf(C_C * x) * (1.0f / C_C);
    float y  = (1.0f - C_A) * t1 + C_A * t2;
    return y * y;
}

__device__ __forceinline__ void cp16(uint32_t d, const void* s) {
    asm volatile("cp.async.cg.shared.global [%0], [%1], 16;"
                 :: "r"(d), "l"(__cvta_generic_to_global(s)) : "memory");
}
__device__ __forceinline__ void cp_commit() {
    asm volatile("cp.async.commit_group;" ::: "memory");
}
template<int N> __device__ __forceinline__ void cp_wait() {
    asm volatile("cp.async.wait_group %0;" :: "n"(N) : "memory");
}
__device__ __forceinline__ void ldsm4(uint32_t* r, uint32_t a) {
    asm volatile("ldmatrix.sync.aligned.m8n8.x4.shared.b16 {%0,%1,%2,%3}, [%4];"
                 : "=r"(r[0]), "=r"(r[1]), "=r"(r[2]), "=r"(r[3]) : "r"(a));
}
__device__ __forceinline__ void mma16816(float* d, const uint32_t* a,
                                         const uint32_t* b) {
    asm volatile(
        "mma.sync.aligned.m16n8k16.row.col.f32.bf16.bf16.f32 "
        "{%0,%1,%2,%3}, {%4,%5,%6,%7}, {%8,%9}, {%0,%1,%2,%3};"
        : "+f"(d[0]), "+f"(d[1]), "+f"(d[2]), "+f"(d[3])
        : "r"(a[0]), "r"(a[1]), "r"(a[2]), "r"(a[3]), "r"(b[0]), "r"(b[1]));
}

// ---------------------------------------------------------------------------
// Kernel 0: fp32 -> bf16 hi/lo split conversion
// ---------------------------------------------------------------------------
__global__ void cvt_kernel(const float4* __restrict__ src,
                           uint2* __restrict__ hi, uint2* __restrict__ lo,
                           int n4) {
    int i = blockIdx.x * blockDim.x + threadIdx.x;
    if (i >= n4) return;
    float4 v = src[i];
    __nv_bfloat162 h01 = __float22bfloat162_rn(make_float2(v.x, v.y));
    __nv_bfloat162 h23 = __float22bfloat162_rn(make_float2(v.z, v.w));
    float2 f01 = __bfloat1622float2(h01);
    float2 f23 = __bfloat1622float2(h23);
    __nv_bfloat162 l01 = __float22bfloat162_rn(make_float2(v.x - f01.x, v.y - f01.y));
    __nv_bfloat162 l23 = __float22bfloat162_rn(make_float2(v.z - f23.x, v.w - f23.y));
    hi[i] = make_uint2(*reinterpret_cast<uint32_t*>(&h01),
                       *reinterpret_cast<uint32_t*>(&h23));
    lo[i] = make_uint2(*reinterpret_cast<uint32_t*>(&l01),
                       *reinterpret_cast<uint32_t*>(&l23));
}

// ---------------------------------------------------------------------------
// Kernel 1: Wsum[h,p,o] = sum_j W[h,p,o,j]
// ---------------------------------------------------------------------------
__global__ void wsum_kernel(const float* __restrict__ W1,
                            const float* __restrict__ W2) {
    int idx  = blockIdx.x * 8 + (threadIdx.x >> 5);
    int lane = threadIdx.x & 31;
    const float* w1 = W1 + (size_t)idx * DD;
    const float* w2 = W2 + (size_t)idx * DD;
    float s1 = warp_sum(w1[lane] + w1[lane + 32]);
    float s2 = warp_sum(w2[lane] + w2[lane + 32]);
    if (lane == 0) { g_Wsum1[idx] = s1; g_Wsum2[idx] = s2; }
}

// ---------------------------------------------------------------------------
// Kernel 2: mma.sync bf16 split GEMM  qk[n,j] = sum_e x[n,e]*qk_w[j,e]
// BM=128, BN=64, KC=32, 256 threads (8 warps, warp tile 32x32).
// D = Ahi*Bhi + Ahi*Blo + Alo*Bhi  (fp32 accum in registers)
// ---------------------------------------------------------------------------
#define BM 128
#define BN 64
#define KC 32
#define RS 80                      // padded smem row stride (bytes)
#define SA_HI 0
#define SA_LO (BM*RS)              // 10240
#define SB_HI (2*BM*RS)            // 20480
#define SB_LO (2*BM*RS + BN*RS)    // 25600
#define STAGE (2*BM*RS + 2*BN*RS)  // 30720
#define SMEMB (2*STAGE)            // 61440

__device__ __forceinline__ void prefetch(uint32_t sbase, int stage,
                                         int tileM, int tileN, int c, int tid) {
    uint32_t st = sbase + (uint32_t)stage * STAGE;
    int kb = c * KC;
#pragma unroll
    for (int i = 0; i < 2; ++i) {
        int idx = tid + i * 256;
        int row = idx >> 2, co = idx & 3;
        size_t goff = (size_t)(tileM * BM + row) * EE + kb + co * 8;
        uint32_t soff = (uint32_t)(row * RS + co * 16);
        cp16(st + SA_HI + soff, g_xhi + goff);
        cp16(st + SA_LO + soff, g_xlo + goff);
    }
    {
        int row = tid >> 2, co = tid & 3;      // 64 rows x 4 col-ops = 256
        size_t goff = (size_t)(tileN * BN + row) * EE + kb + co * 8;
        uint32_t soff = (uint32_t)(row * RS + co * 16);
        cp16(st + SB_HI + soff, g_whi + goff);
        cp16(st + SB_LO + soff, g_wlo + goff);
    }
}

__global__ __launch_bounds__(256, 2)
void qk_gemm_mma(float* __restrict__ out) {
    extern __shared__ char dsm[];
    uint32_t sbase = smem_u32(dsm);
    int tid = threadIdx.x, wid = tid >> 5, lane = tid & 31;
    int tileN = blockIdx.x, tileM = blockIdx.y;

    float acc[2][4][4];
#pragma unroll
    for (int a = 0; a < 2; ++a)
#pragma unroll
        for (int b = 0; b < 4; ++b)
#pragma unroll
            for (int cc = 0; cc < 4; ++cc) acc[a][b][cc] = 0.0f;

    prefetch(sbase, 0, tileM, tileN, 0, tid);
    cp_commit();

    int wm = (wid & 3) * 32;   // warp M offset in tile
    int wn = (wid >> 2) * 32;  // warp N offset in tile
    int r8 = lane & 7, sub = lane >> 3;

    for (int c = 0; c < EE / KC; ++c) {
        if (c + 1 < EE / KC) {
            prefetch(sbase, (c + 1) & 1, tileM, tileN, c + 1, tid);
            cp_commit();
            cp_wait<1>();
        } else {
            cp_wait<0>();
        }
        __syncthreads();
        uint32_t st = sbase + (uint32_t)(c & 1) * STAGE;

#pragma unroll
        for (int kk = 0; kk < 2; ++kk) {    // two k16 steps per KC=32
            uint32_t ah[2][4], al[2][4], bh[4][2], bl[4][2];
#pragma unroll
            for (int mt = 0; mt < 2; ++mt) {
                uint32_t ra = st + SA_HI +
                    (uint32_t)((wm + mt * 16 + r8 + (sub & 1) * 8) * RS +
                               kk * 32 + (sub >> 1) * 16);
                ldsm4(ah[mt], ra);
                ldsm4(al[mt], ra + (SA_LO - SA_HI));
            }
#pragma unroll
            for (int p = 0; p < 2; ++p) {
                uint32_t rb = st + SB_HI +
                    (uint32_t)((wn + p * 16 + r8 + (sub >> 1) * 8) * RS +
                               kk * 32 + (sub & 1) * 16);
                uint32_t t4[4];
                ldsm4(t4, rb);
                bh[2 * p][0] = t4[0]; bh[2 * p][1] = t4[1];
                bh[2 * p + 1][0] = t4[2]; bh[2 * p + 1][1] = t4[3];
                ldsm4(t4, rb + (SB_LO - SB_HI));
                bl[2 * p][0] = t4[0]; bl[2 * p][1] = t4[1];
                bl[2 * p + 1][0] = t4[2]; bl[2 * p + 1][1] = t4[3];
            }
#pragma unroll
            for (int mt = 0; mt < 2; ++mt)
#pragma unroll
                for (int nt = 0; nt < 4; ++nt) {
                    mma16816(acc[mt][nt], ah[mt], bh[nt]);
                    mma16816(acc[mt][nt], ah[mt], bl[nt]);
                    mma16816(acc[mt][nt], al[mt], bh[nt]);
                }
        }
        __syncthreads();
    }

    // epilogue: fragment (g = lane>>2 row, 2*(lane&3) col pair) -> q/k scatter
    int g = lane >> 2, t2 = (lane & 3) * 2;
#pragma unroll
    for (int mt = 0; mt < 2; ++mt) {
        int mrow0 = tileM * BM + wm + mt * 16 + g;
#pragma unroll
        for (int half = 0; half < 2; ++half) {
            int m = mrow0 + half * 8;
            int b_ = m >> 11;
            int s_ = m & (SS - 1);
#pragma unroll
            for (int nt = 0; nt < 4; ++nt) {
                int j = tileN * BN + wn + nt * 8 + t2;
                size_t toff = (j >= EE) ? (size_t)QSIZE : 0;
                int jc = j & (EE - 1);
                int h  = jc >> 6;
                int d0 = jc & 63;
                float* op = out + toff +
                            (((size_t)b_ * HH + h) * SS + s_) * DD + d0;
                float2 w = make_float2(acc[mt][nt][half * 2 + 0],
                                       acc[mt][nt][half * 2 + 1]);
                *(float2*)op = w;
            }
        }
    }
}

// ---------------------------------------------------------------------------
// Kernel 3: fused vector-hull (unchanged from R3)
// ---------------------------------------------------------------------------
#define TOKS_PER_WARP 4

__global__ __launch_bounds__(256)
void vhull_kernel(const float* __restrict__ x,
                  const float* __restrict__ b1,
                  const float* __restrict__ b2,
                  const float* __restrict__ gate_w,
                  const float* __restrict__ gate_b,
                  float* __restrict__ vout) {
    __shared__ float sW1[PP * DD];
    __shared__ float sB1[PP * DD];
    __shared__ float sW2[PP * DD];
    __shared__ float sB2[PP * DD];
    __shared__ float sGw[DD];

    int h = blockIdx.y;
    for (int i = threadIdx.x; i < PP * DD; i += 256) {
        sW1[i] = g_Wsum1[h * PP * DD + i];
        sB1[i] = b1[h * PP * DD + i];
        sW2[i] = g_Wsum2[h * PP * DD + i];
        sB2[i] = b2[h * PP * DD + i];
    }
    if (threadIdx.x < DD) sGw[threadIdx.x] = gate_w[h * DD + threadIdx.x];
    float gb = gate_b[h];
    __syncthreads();

    int warp = threadIdx.x >> 5;
    int lane = threadIdx.x & 31;
    int tokBase = (blockIdx.x * 8 + warp) * TOKS_PER_WARP;

    for (int t = 0; t < TOKS_PER_WARP; ++t) {
        int n = tokBase + t;
        const float* xp = x + (size_t)n * EE + h * DD;
        float xh0 = xp[lane];
        float xh1 = xp[lane + 32];

        float dot = warp_sum(xh0 * sGw[lane] + xh1 * sGw[lane + 32]);
        float u = sqspf(dot + gb);
        float g = 1.0f - __expf(-u);
        float xg0 = xh0 * g;
        float xg1 = xh1 * g;

        float s  = warp_sum(xg0 + xg1);
        float q2 = warp_sum(xg0 * xg0 + xg1 * xg1);
        float tau = sqrtf(q2 * (1.0f / DD) + C_EPS + C_NU);
        float inv_tau = 1.0f / tau;

        float tp[PP];
#pragma unroll
        for (int p = 0; p < PP; ++p) {
            int i0 = p * DD + lane;
            float z0 = sqspf(fmaf(s, sW1[i0],      sB1[i0]));
            float z1 = sqspf(fmaf(s, sW1[i0 + 32], sB1[i0 + 32]));
            tp[p] = warp_sum(z0 + z1);
        }

        float vres[2];
#pragma unroll
        for (int oo = 0; oo < 2; ++oo) {
            int o = lane + oo * 32;
            float a[PP];
            float m = -3.4e38f;
#pragma unroll
            for (int p = 0; p < PP; ++p) {
                a[p] = sqspf(fmaf(tp[p], sW2[p * DD + o], sB2[p * DD + o]));
                m = fmaxf(m, a[p]);
            }
            float sume = 0.0f;
#pragma unroll
            for (int p = 0; p < PP; ++p)
                sume += __expf((a[p] - m) * tau);
            vres[oo] = m + __logf(sume) * inv_tau;
        }

        int b_ = n >> 11;
        int s_ = n & (SS - 1);
        float* op = vout + (((size_t)b_ * HH + h) * SS + s_) * DD;
        op[lane]      = vres[0];
        op[lane + 32] = vres[1];
    }
}

// ---------------------------------------------------------------------------
// launch
// ---------------------------------------------------------------------------
extern "C" void kernel_launch(void* const* d_in, const int* in_sizes, int n_in,
                              void* d_out, int out_size) {
    const float* x      = (const float*)d_in[0];
    const float* qk_w   = (const float*)d_in[1];
    const float* W1     = (const float*)d_in[2];
    const float* b1     = (const float*)d_in[3];
    const float* W2     = (const float*)d_in[4];
    const float* b2     = (const float*)d_in[5];
    const float* gate_w = (const float*)d_in[6];
    const float* gate_b = (const float*)d_in[7];
    float* out = (float*)d_out;

    // resolve scratch addresses
    __nv_bfloat16 *xhi_p, *xlo_p, *whi_p, *wlo_p;
    cudaGetSymbolAddress((void**)&xhi_p, g_xhi);
    cudaGetSymbolAddress((void**)&xlo_p, g_xlo);
    cudaGetSymbolAddress((void**)&whi_p, g_whi);
    cudaGetSymbolAddress((void**)&wlo_p, g_wlo);

    // convert x and qk_w to bf16 hi/lo
    {
        int n4 = NTOK * EE / 4;
        cvt_kernel<<<(n4 + 255) / 256, 256>>>((const float4*)x,
                                              (uint2*)xhi_p, (uint2*)xlo_p, n4);
        int m4 = NQK * EE / 4;
        cvt_kernel<<<(m4 + 255) / 256, 256>>>((const float4*)qk_w,
                                              (uint2*)whi_p, (uint2*)wlo_p, m4);
    }

    wsum_kernel<<<1024, 256>>>(W1, W2);

    static int smem_set = 0;
    cudaFuncSetAttribute(qk_gemm_mma,
                         cudaFuncAttributeMaxDynamicSharedMemorySize, SMEMB);
    (void)smem_set;
    dim3 ggrid(NQK / BN, NTOK / BM);   // (32, 64)
    qk_gemm_mma<<<ggrid, 256, SMEMB>>>(out);

    dim3 vgrid(NTOK / (8 * TOKS_PER_WARP), HH);
    vhull_kernel<<<vgrid, 256>>>(x, b1, b2, gate_w, gate_b,
                                 out + 2 * (size_t)QSIZE);
}

// round 7
// speedup vs baseline: 2.2227x; 1.1908x over previous
// R7: resubmission of R6 (broker infra failed twice; kernel never ran).
// fp16 2-product split (A corrected, B hi-only) + 3-stage cp.async pipeline.
#include <cuda_runtime.h>
#include <cuda_fp16.h>
#include <cstdint>

// Problem constants
#define BB 4
#define SS 2048
#define EE 1024
#define HH 16
#define PP 8
#define DD 64
#define NTOK (BB*SS)          // 8192
#define QSIZE (BB*HH*SS*DD)   // 8,388,608 floats per tensor (q, k, v)
#define NQK 2048              // rows of qk_w

// SqSoftplus constants
#define C_B 2.0480546988460353f
#define C_C 0.841470984807896f
#define C_A 0.45339765151640377f
#define C_NU 0.999999327348f   // log(2.71828)
#define C_EPS 1e-6f

// ---------------------------------------------------------------------------
// Scratch
// ---------------------------------------------------------------------------
__device__ float g_Wsum1[HH*PP*DD];
__device__ float g_Wsum2[HH*PP*DD];
__device__ __half g_xhi[(size_t)NTOK*EE];
__device__ __half g_xlo[(size_t)NTOK*EE];
__device__ __half g_whi[(size_t)NQK*EE];

// ---------------------------------------------------------------------------
// helpers
// ---------------------------------------------------------------------------
__device__ __forceinline__ uint32_t smem_u32(const void* p) {
    uint32_t a;
    asm("{ .reg .u64 t; cvta.to.shared.u64 t, %1; cvt.u32.u64 %0, t; }"
        : "=r"(a) : "l"(p));
    return a;
}
__device__ __forceinline__ float warp_sum(float v) {
#pragma unroll
    for (int o = 16; o; o >>= 1) v += __shfl_xor_sync(0xffffffffu, v, o);
    return v;
}
__device__ __forceinline__ float softplusf(float z) {
    float az = fabsf(z);
    float e  = __expf(-az);
    return fmaxf(z, 0.0f) + __logf(1.0f + e);
}
__device__ __forceinline__ float sqspf(float x) {
    float t1 = softplusf(C_B * x) * (1.0f / C_B);
    float t2 = softplusf(C_C * x) * (1.0f / C_C);
    float y  = (1.0f - C_A) * t1 + C_A * t2;
    return y * y;
}

__device__ __forceinline__ void cp16(uint32_t d, const void* s) {
    asm volatile("cp.async.cg.shared.global [%0], [%1], 16;"
                 :: "r"(d), "l"(__cvta_generic_to_global(s)) : "memory");
}
__device__ __forceinline__ void cp_commit() {
    asm volatile("cp.async.commit_group;" ::: "memory");
}
template<int N> __device__ __forceinline__ void cp_wait() {
    asm volatile("cp.async.wait_group %0;" :: "n"(N) : "memory");
}
__device__ __forceinline__ void ldsm4(uint32_t* r, uint32_t a) {
    asm volatile("ldmatrix.sync.aligned.m8n8.x4.shared.b16 {%0,%1,%2,%3}, [%4];"
                 : "=r"(r[0]), "=r"(r[1]), "=r"(r[2]), "=r"(r[3]) : "r"(a));
}
__device__ __forceinline__ void mma16816(float* d, const uint32_t* a,
                                         const uint32_t* b) {
    asm volatile(
        "mma.sync.aligned.m16n8k16.row.col.f32.f16.f16.f32 "
        "{%0,%1,%2,%3}, {%4,%5,%6,%7}, {%8,%9}, {%0,%1,%2,%3};"
        : "+f"(d[0]), "+f"(d[1]), "+f"(d[2]), "+f"(d[3])
        : "r"(a[0]), "r"(a[1]), "r"(a[2]), "r"(a[3]), "r"(b[0]), "r"(b[1]));
}

// ---------------------------------------------------------------------------
// Kernel 0a: fp32 -> fp16 hi/lo split (for x)
// ---------------------------------------------------------------------------
__global__ void cvt_split_kernel(const float4* __restrict__ src,
                                 uint2* __restrict__ hi, uint2* __restrict__ lo,
                                 int n4) {
    int i = blockIdx.x * blockDim.x + threadIdx.x;
    if (i >= n4) return;
    float4 v = src[i];
    __half2 h01 = __float22half2_rn(make_float2(v.x, v.y));
    __half2 h23 = __float22half2_rn(make_float2(v.z, v.w));
    float2 f01 = __half22float2(h01);
    float2 f23 = __half22float2(h23);
    __half2 l01 = __float22half2_rn(make_float2(v.x - f01.x, v.y - f01.y));
    __half2 l23 = __float22half2_rn(make_float2(v.z - f23.x, v.w - f23.y));
    hi[i] = make_uint2(*reinterpret_cast<uint32_t*>(&h01),
                       *reinterpret_cast<uint32_t*>(&h23));
    lo[i] = make_uint2(*reinterpret_cast<uint32_t*>(&l01),
                       *reinterpret_cast<uint32_t*>(&l23));
}

// Kernel 0b: fp32 -> fp16 hi only (for qk_w)
__global__ void cvt_hi_kernel(const float4* __restrict__ src,
                              uint2* __restrict__ hi, int n4) {
    int i = blockIdx.x * blockDim.x + threadIdx.x;
    if (i >= n4) return;
    float4 v = src[i];
    __half2 h01 = __float22half2_rn(make_float2(v.x, v.y));
    __half2 h23 = __float22half2_rn(make_float2(v.z, v.w));
    hi[i] = make_uint2(*reinterpret_cast<uint32_t*>(&h01),
                       *reinterpret_cast<uint32_t*>(&h23));
}

// ---------------------------------------------------------------------------
// Kernel 1: Wsum[h,p,o] = sum_j W[h,p,o,j]
// ---------------------------------------------------------------------------
__global__ void wsum_kernel(const float* __restrict__ W1,
                            const float* __restrict__ W2) {
    int idx  = blockIdx.x * 8 + (threadIdx.x >> 5);
    int lane = threadIdx.x & 31;
    const float* w1 = W1 + (size_t)idx * DD;
    const float* w2 = W2 + (size_t)idx * DD;
    float s1 = warp_sum(w1[lane] + w1[lane + 32]);
    float s2 = warp_sum(w2[lane] + w2[lane + 32]);
    if (lane == 0) { g_Wsum1[idx] = s1; g_Wsum2[idx] = s2; }
}

// ---------------------------------------------------------------------------
// Kernel 2: mma.sync fp16 split GEMM  qk[n,j] = sum_e x[n,e]*qk_w[j,e]
// BM=128, BN=64, KC=32, 256 threads, warp tile 32x32, 3-stage pipeline.
// D = (Ahi + Alo) * Bhi   (2 MMA products, fp32 accum)
// ---------------------------------------------------------------------------
#define BM 128
#define BN 64
#define KC 32
#define RS 80                      // padded smem row stride (bytes)
#define SA_HI 0
#define SA_LO (BM*RS)              // 10240
#define SB_HI (2*BM*RS)            // 20480
#define STAGE (2*BM*RS + BN*RS)    // 25600
#define NSTAGE 3
#define SMEMB (NSTAGE*STAGE)       // 76800
#define NCH (EE/KC)                // 32

__device__ __forceinline__ void prefetch(uint32_t sbase, int stage,
                                         int tileM, int tileN, int c, int tid) {
    uint32_t st = sbase + (uint32_t)stage * STAGE;
    int kb = c * KC;
#pragma unroll
    for (int i = 0; i < 2; ++i) {
        int idx = tid + i * 256;
        int row = idx >> 2, co = idx & 3;
        size_t goff = (size_t)(tileM * BM + row) * EE + kb + co * 8;
        uint32_t soff = (uint32_t)(row * RS + co * 16);
        cp16(st + SA_HI + soff, g_xhi + goff);
        cp16(st + SA_LO + soff, g_xlo + goff);
    }
    {
        int row = tid >> 2, co = tid & 3;      // 64 rows x 4 col-ops = 256
        size_t goff = (size_t)(tileN * BN + row) * EE + kb + co * 8;
        uint32_t soff = (uint32_t)(row * RS + co * 16);
        cp16(st + SB_HI + soff, g_whi + goff);
    }
}

__global__ __launch_bounds__(256, 2)
void qk_gemm_mma(float* __restrict__ out) {
    extern __shared__ char dsm[];
    uint32_t sbase = smem_u32(dsm);
    int tid = threadIdx.x, wid = tid >> 5, lane = tid & 31;
    int tileN = blockIdx.x, tileM = blockIdx.y;

    float acc[2][4][4];
#pragma unroll
    for (int a = 0; a < 2; ++a)
#pragma unroll
        for (int b = 0; b < 4; ++b)
#pragma unroll
            for (int cc = 0; cc < 4; ++cc) acc[a][b][cc] = 0.0f;

    prefetch(sbase, 0, tileM, tileN, 0, tid);
    cp_commit();
    prefetch(sbase, 1, tileM, tileN, 1, tid);
    cp_commit();

    int wm = (wid & 3) * 32;   // warp M offset in tile
    int wn = (wid >> 2) * 32;  // warp N offset in tile
    int r8 = lane & 7, sub = lane >> 3;

    int stage = 0;
    for (int c = 0; c < NCH; ++c) {
        cp_wait<1>();            // group c complete
        __syncthreads();
        if (c + 2 < NCH)
            prefetch(sbase, (stage + 2) % NSTAGE, tileM, tileN, c + 2, tid);
        cp_commit();             // always commit (keeps group count exact)

        uint32_t st = sbase + (uint32_t)stage * STAGE;
#pragma unroll
        for (int kk = 0; kk < 2; ++kk) {    // two k16 steps per KC=32
            uint32_t ah[2][4], al[2][4], bh[4][2];
#pragma unroll
            for (int mt = 0; mt < 2; ++mt) {
                uint32_t ra = st + SA_HI +
                    (uint32_t)((wm + mt * 16 + r8 + (sub & 1) * 8) * RS +
                               kk * 32 + (sub >> 1) * 16);
                ldsm4(ah[mt], ra);
                ldsm4(al[mt], ra + (SA_LO - SA_HI));
            }
#pragma unroll
            for (int p = 0; p < 2; ++p) {
                uint32_t rb = st + SB_HI +
                    (uint32_t)((wn + p * 16 + r8 + (sub >> 1) * 8) * RS +
                               kk * 32 + (sub & 1) * 16);
                uint32_t t4[4];
                ldsm4(t4, rb);
                bh[2 * p][0] = t4[0]; bh[2 * p][1] = t4[1];
                bh[2 * p + 1][0] = t4[2]; bh[2 * p + 1][1] = t4[3];
            }
#pragma unroll
            for (int mt = 0; mt < 2; ++mt)
#pragma unroll
                for (int nt = 0; nt < 4; ++nt) {
                    mma16816(acc[mt][nt], ah[mt], bh[nt]);
                    mma16816(acc[mt][nt], al[mt], bh[nt]);
                }
        }
        stage = (stage + 1) % NSTAGE;
    }

    // epilogue: fragment (g = lane>>2 row, 2*(lane&3) col pair) -> q/k scatter
    int g = lane >> 2, t2 = (lane & 3) * 2;
#pragma unroll
    for (int mt = 0; mt < 2; ++mt) {
        int mrow0 = tileM * BM + wm + mt * 16 + g;
#pragma unroll
        for (int half = 0; half < 2; ++half) {
            int m = mrow0 + half * 8;
            int b_ = m >> 11;
            int s_ = m & (SS - 1);
#pragma unroll
            for (int nt = 0; nt < 4; ++nt) {
                int j = tileN * BN + wn + nt * 8 + t2;
                size_t toff = (j >= EE) ? (size_t)QSIZE : 0;
                int jc = j & (EE - 1);
                int h  = jc >> 6;
                int d0 = jc & 63;
                float* op = out + toff +
                            (((size_t)b_ * HH + h) * SS + s_) * DD + d0;
                float2 w = make_float2(acc[mt][nt][half * 2 + 0],
                                       acc[mt][nt][half * 2 + 1]);
                *(float2*)op = w;
            }
        }
    }
}

// ---------------------------------------------------------------------------
// Kernel 3: fused vector-hull (unchanged)
// ---------------------------------------------------------------------------
#define TOKS_PER_WARP 4

__global__ __launch_bounds__(256)
void vhull_kernel(const float* __restrict__ x,
                  const float* __restrict__ b1,
                  const float* __restrict__ b2,
                  const float* __restrict__ gate_w,
                  const float* __restrict__ gate_b,
                  float* __restrict__ vout) {
    __shared__ float sW1[PP * DD];
    __shared__ float sB1[PP * DD];
    __shared__ float sW2[PP * DD];
    __shared__ float sB2[PP * DD];
    __shared__ float sGw[DD];

    int h = blockIdx.y;
    for (int i = threadIdx.x; i < PP * DD; i += 256) {
        sW1[i] = g_Wsum1[h * PP * DD + i];
        sB1[i] = b1[h * PP * DD + i];
        sW2[i] = g_Wsum2[h * PP * DD + i];
        sB2[i] = b2[h * PP * DD + i];
    }
    if (threadIdx.x < DD) sGw[threadIdx.x] = gate_w[h * DD + threadIdx.x];
    float gb = gate_b[h];
    __syncthreads();

    int warp = threadIdx.x >> 5;
    int lane = threadIdx.x & 31;
    int tokBase = (blockIdx.x * 8 + warp) * TOKS_PER_WARP;

    for (int t = 0; t < TOKS_PER_WARP; ++t) {
        int n = tokBase + t;
        const float* xp = x + (size_t)n * EE + h * DD;
        float xh0 = xp[lane];
        float xh1 = xp[lane + 32];

        float dot = warp_sum(xh0 * sGw[lane] + xh1 * sGw[lane + 32]);
        float u = sqspf(dot + gb);
        float g = 1.0f - __expf(-u);
        float xg0 = xh0 * g;
        float xg1 = xh1 * g;

        float s  = warp_sum(xg0 + xg1);
        float q2 = warp_sum(xg0 * xg0 + xg1 * xg1);
        float tau = sqrtf(q2 * (1.0f / DD) + C_EPS + C_NU);
        float inv_tau = 1.0f / tau;

        float tp[PP];
#pragma unroll
        for (int p = 0; p < PP; ++p) {
            int i0 = p * DD + lane;
            float z0 = sqspf(fmaf(s, sW1[i0],      sB1[i0]));
            float z1 = sqspf(fmaf(s, sW1[i0 + 32], sB1[i0 + 32]));
            tp[p] = warp_sum(z0 + z1);
        }

        float vres[2];
#pragma unroll
        for (int oo = 0; oo < 2; ++oo) {
            int o = lane + oo * 32;
            float a[PP];
            float m = -3.4e38f;
#pragma unroll
            for (int p = 0; p < PP; ++p) {
                a[p] = sqspf(fmaf(tp[p], sW2[p * DD + o], sB2[p * DD + o]));
                m = fmaxf(m, a[p]);
            }
            float sume = 0.0f;
#pragma unroll
            for (int p = 0; p < PP; ++p)
                sume += __expf((a[p] - m) * tau);
            vres[oo] = m + __logf(sume) * inv_tau;
        }

        int b_ = n >> 11;
        int s_ = n & (SS - 1);
        float* op = vout + (((size_t)b_ * HH + h) * SS + s_) * DD;
        op[lane]      = vres[0];
        op[lane + 32] = vres[1];
    }
}

// ---------------------------------------------------------------------------
// launch
// ---------------------------------------------------------------------------
extern "C" void kernel_launch(void* const* d_in, const int* in_sizes, int n_in,
                              void* d_out, int out_size) {
    const float* x      = (const float*)d_in[0];
    const float* qk_w   = (const float*)d_in[1];
    const float* W1     = (const float*)d_in[2];
    const float* b1     = (const float*)d_in[3];
    const float* W2     = (const float*)d_in[4];
    const float* b2     = (const float*)d_in[5];
    const float* gate_w = (const float*)d_in[6];
    const float* gate_b = (const float*)d_in[7];
    float* out = (float*)d_out;

    __half *xhi_p, *xlo_p, *whi_p;
    cudaGetSymbolAddress((void**)&xhi_p, g_xhi);
    cudaGetSymbolAddress((void**)&xlo_p, g_xlo);
    cudaGetSymbolAddress((void**)&whi_p, g_whi);

    {
        int n4 = NTOK * EE / 4;
        cvt_split_kernel<<<(n4 + 255) / 256, 256>>>((const float4*)x,
                                                    (uint2*)xhi_p, (uint2*)xlo_p, n4);
        int m4 = NQK * EE / 4;
        cvt_hi_kernel<<<(m4 + 255) / 256, 256>>>((const float4*)qk_w,
                                                 (uint2*)whi_p, m4);
    }

    wsum_kernel<<<1024, 256>>>(W1, W2);

    cudaFuncSetAttribute(qk_gemm_mma,
                         cudaFuncAttributeMaxDynamicSharedMemorySize, SMEMB);
    dim3 ggrid(NQK / BN, NTOK / BM);   // (32, 64)
    qk_gemm_mma<<<ggrid, 256, SMEMB>>>(out);

    dim3 vgrid(NTOK / (8 * TOKS_PER_WARP), HH);
    vhull_kernel<<<vgrid, 256>>>(x, b1, b2, gate_w, gate_b,
                                 out + 2 * (size_t)QSIZE);
}

// round 10
// speedup vs baseline: 2.9718x; 1.3370x over previous
// R10: second resubmission of the R8 kernel (broker failed 2x twice; this
// exact content never ran on HW; R6->R7 precedent says infra is stochastic).
// GEMM tile 128x128 (warp 32x64) + vhull softplus saturation fast-path.
#include <cuda_runtime.h>
#include <cuda_fp16.h>
#include <cstdint>

#define BB 4
#define SS 2048
#define EE 1024
#define HH 16
#define PP 8
#define DD 64
#define NTOK (BB*SS)          // 8192
#define QSIZE (BB*HH*SS*DD)   // 8,388,608 floats per tensor
#define NQK 2048

#define C_B 2.0480546988460353f
#define C_C 0.841470984807896f
#define C_A 0.45339765151640377f
#define C_NU 0.999999327348f
#define C_EPS 1e-6f

// ---------------------------------------------------------------------------
// Scratch
// ---------------------------------------------------------------------------
__device__ float g_Wsum1[HH*PP*DD];
__device__ float g_Wsum2[HH*PP*DD];
__device__ __half g_xhi[(size_t)NTOK*EE];
__device__ __half g_xlo[(size_t)NTOK*EE];
__device__ __half g_whi[(size_t)NQK*EE];

// ---------------------------------------------------------------------------
// helpers
// ---------------------------------------------------------------------------
__device__ __forceinline__ uint32_t smem_u32(const void* p) {
    uint32_t a;
    asm("{ .reg .u64 t; cvta.to.shared.u64 t, %1; cvt.u32.u64 %0, t; }"
        : "=r"(a) : "l"(p));
    return a;
}
__device__ __forceinline__ float warp_sum(float v) {
#pragma unroll
    for (int o = 16; o; o >>= 1) v += __shfl_xor_sync(0xffffffffu, v, o);
    return v;
}
__device__ __forceinline__ float softplusf(float z) {
    float az = fabsf(z);
    float e  = __expf(-az);
    return fmaxf(z, 0.0f) + __logf(1.0f + e);
}
__device__ __forceinline__ float sqspf(float x) {
    float t1 = softplusf(C_B * x) * (1.0f / C_B);
    float t2 = softplusf(C_C * x) * (1.0f / C_C);
    float y  = (1.0f - C_A) * t1 + C_A * t2;
    return y * y;
}
// saturated sqsp: exact for |z| >= 16 (softplus error < 2e-7 there)
__device__ __forceinline__ float sqsp_cheap(float z) {
    float p = fmaxf(z, 0.0f);
    return p * p;
}

__device__ __forceinline__ void cp16(uint32_t d, const void* s) {
    asm volatile("cp.async.cg.shared.global [%0], [%1], 16;"
                 :: "r"(d), "l"(__cvta_generic_to_global(s)) : "memory");
}
__device__ __forceinline__ void cp_commit() {
    asm volatile("cp.async.commit_group;" ::: "memory");
}
template<int N> __device__ __forceinline__ void cp_wait() {
    asm volatile("cp.async.wait_group %0;" :: "n"(N) : "memory");
}
__device__ __forceinline__ void ldsm4(uint32_t* r, uint32_t a) {
    asm volatile("ldmatrix.sync.aligned.m8n8.x4.shared.b16 {%0,%1,%2,%3}, [%4];"
                 : "=r"(r[0]), "=r"(r[1]), "=r"(r[2]), "=r"(r[3]) : "r"(a));
}
__device__ __forceinline__ void mma16816(float* d, const uint32_t* a,
                                         const uint32_t* b) {
    asm volatile(
        "mma.sync.aligned.m16n8k16.row.col.f32.f16.f16.f32 "
        "{%0,%1,%2,%3}, {%4,%5,%6,%7}, {%8,%9}, {%0,%1,%2,%3};"
        : "+f"(d[0]), "+f"(d[1]), "+f"(d[2]), "+f"(d[3])
        : "r"(a[0]), "r"(a[1]), "r"(a[2]), "r"(a[3]), "r"(b[0]), "r"(b[1]));
}

// ---------------------------------------------------------------------------
// Kernel 0a/0b: fp32 -> fp16 conversions
// ---------------------------------------------------------------------------
__global__ void cvt_split_kernel(const float4* __restrict__ src,
                                 uint2* __restrict__ hi, uint2* __restrict__ lo,
                                 int n4) {
    int i = blockIdx.x * blockDim.x + threadIdx.x;
    if (i >= n4) return;
    float4 v = src[i];
    __half2 h01 = __float22half2_rn(make_float2(v.x, v.y));
    __half2 h23 = __float22half2_rn(make_float2(v.z, v.w));
    float2 f01 = __half22float2(h01);
    float2 f23 = __half22float2(h23);
    __half2 l01 = __float22half2_rn(make_float2(v.x - f01.x, v.y - f01.y));
    __half2 l23 = __float22half2_rn(make_float2(v.z - f23.x, v.w - f23.y));
    hi[i] = make_uint2(*reinterpret_cast<uint32_t*>(&h01),
                       *reinterpret_cast<uint32_t*>(&h23));
    lo[i] = make_uint2(*reinterpret_cast<uint32_t*>(&l01),
                       *reinterpret_cast<uint32_t*>(&l23));
}
__global__ void cvt_hi_kernel(const float4* __restrict__ src,
                              uint2* __restrict__ hi, int n4) {
    int i = blockIdx.x * blockDim.x + threadIdx.x;
    if (i >= n4) return;
    float4 v = src[i];
    __half2 h01 = __float22half2_rn(make_float2(v.x, v.y));
    __half2 h23 = __float22half2_rn(make_float2(v.z, v.w));
    hi[i] = make_uint2(*reinterpret_cast<uint32_t*>(&h01),
                       *reinterpret_cast<uint32_t*>(&h23));
}

// ---------------------------------------------------------------------------
// Kernel 1: Wsum[h,p,o] = sum_j W[h,p,o,j]
// ---------------------------------------------------------------------------
__global__ void wsum_kernel(const float* __restrict__ W1,
                            const float* __restrict__ W2) {
    int idx  = blockIdx.x * 8 + (threadIdx.x >> 5);
    int lane = threadIdx.x & 31;
    const float* w1 = W1 + (size_t)idx * DD;
    const float* w2 = W2 + (size_t)idx * DD;
    float s1 = warp_sum(w1[lane] + w1[lane + 32]);
    float s2 = warp_sum(w2[lane] + w2[lane + 32]);
    if (lane == 0) { g_Wsum1[idx] = s1; g_Wsum2[idx] = s2; }
}

// ---------------------------------------------------------------------------
// Kernel 2: fp16 split GEMM, tile 128x128, warp tile 32x64, 3-stage pipeline
// D = (Ahi + Alo) * Bhi
// ---------------------------------------------------------------------------
#define BM 128
#define BN 128
#define KC 32
#define RS 80
#define SA_HI 0
#define SA_LO (BM*RS)              // 10240
#define SB_HI (2*BM*RS)            // 20480
#define STAGE (2*BM*RS + BN*RS)    // 30720
#define NSTAGE 3
#define SMEMB (NSTAGE*STAGE)       // 92160
#define NCH (EE/KC)                // 32

__device__ __forceinline__ void prefetch(uint32_t sbase, int stage,
                                         int tileM, int tileN, int c, int tid) {
    uint32_t st = sbase + (uint32_t)stage * STAGE;
    int kb = c * KC;
#pragma unroll
    for (int i = 0; i < 2; ++i) {
        int idx = tid + i * 256;
        int row = idx >> 2, co = idx & 3;
        size_t goff = (size_t)(tileM * BM + row) * EE + kb + co * 8;
        uint32_t soff = (uint32_t)(row * RS + co * 16);
        cp16(st + SA_HI + soff, g_xhi + goff);
        cp16(st + SA_LO + soff, g_xlo + goff);
    }
#pragma unroll
    for (int i = 0; i < 2; ++i) {
        int idx = tid + i * 256;
        int row = idx >> 2, co = idx & 3;
        size_t goff = (size_t)(tileN * BN + row) * EE + kb + co * 8;
        uint32_t soff = (uint32_t)(row * RS + co * 16);
        cp16(st + SB_HI + soff, g_whi + goff);
    }
}

__global__ __launch_bounds__(256, 2)
void qk_gemm_mma(float* __restrict__ out) {
    extern __shared__ char dsm[];
    uint32_t sbase = smem_u32(dsm);
    int tid = threadIdx.x, wid = tid >> 5, lane = tid & 31;
    int tileN = blockIdx.x, tileM = blockIdx.y;

    float acc[2][8][4];
#pragma unroll
    for (int a = 0; a < 2; ++a)
#pragma unroll
        for (int b = 0; b < 8; ++b)
#pragma unroll
            for (int cc = 0; cc < 4; ++cc) acc[a][b][cc] = 0.0f;

    prefetch(sbase, 0, tileM, tileN, 0, tid);
    cp_commit();
    prefetch(sbase, 1, tileM, tileN, 1, tid);
    cp_commit();

    int wm = (wid & 3) * 32;   // 4 warps across M
    int wn = (wid >> 2) * 64;  // 2 warps across N
    int r8 = lane & 7, sub = lane >> 3;

    int stage = 0;
    for (int c = 0; c < NCH; ++c) {
        cp_wait<1>();
        __syncthreads();
        if (c + 2 < NCH)
            prefetch(sbase, (stage + 2) % NSTAGE, tileM, tileN, c + 2, tid);
        cp_commit();

        uint32_t st = sbase + (uint32_t)stage * STAGE;
#pragma unroll
        for (int kk = 0; kk < 2; ++kk) {
            uint32_t ah[2][4], al[2][4], bh[8][2];
#pragma unroll
            for (int mt = 0; mt < 2; ++mt) {
                uint32_t ra = st + SA_HI +
                    (uint32_t)((wm + mt * 16 + r8 + (sub & 1) * 8) * RS +
                               kk * 32 + (sub >> 1) * 16);
                ldsm4(ah[mt], ra);
                ldsm4(al[mt], ra + (SA_LO - SA_HI));
            }
#pragma unroll
            for (int p = 0; p < 4; ++p) {
                uint32_t rb = st + SB_HI +
                    (uint32_t)((wn + p * 16 + r8 + (sub >> 1) * 8) * RS +
                               kk * 32 + (sub & 1) * 16);
                uint32_t t4[4];
                ldsm4(t4, rb);
                bh[2 * p][0] = t4[0]; bh[2 * p][1] = t4[1];
                bh[2 * p + 1][0] = t4[2]; bh[2 * p + 1][1] = t4[3];
            }
#pragma unroll
            for (int mt = 0; mt < 2; ++mt)
#pragma unroll
                for (int nt = 0; nt < 8; ++nt) {
                    mma16816(acc[mt][nt], ah[mt], bh[nt]);
                    mma16816(acc[mt][nt], al[mt], bh[nt]);
                }
        }
        stage = (stage + 1) % NSTAGE;
    }

    // epilogue -> q/k (B,H,S,D) scatter
    int g = lane >> 2, t2 = (lane & 3) * 2;
#pragma unroll
    for (int mt = 0; mt < 2; ++mt) {
        int mrow0 = tileM * BM + wm + mt * 16 + g;
#pragma unroll
        for (int half = 0; half < 2; ++half) {
            int m = mrow0 + half * 8;
            int b_ = m >> 11;
            int s_ = m & (SS - 1);
#pragma unroll
            for (int nt = 0; nt < 8; ++nt) {
                int j = tileN * BN + wn + nt * 8 + t2;
                size_t toff = (j >= EE) ? (size_t)QSIZE : 0;
                int jc = j & (EE - 1);
                int h  = jc >> 6;
                int d0 = jc & 63;
                float* op = out + toff +
                            (((size_t)b_ * HH + h) * SS + s_) * DD + d0;
                float2 w = make_float2(acc[mt][nt][half * 2 + 0],
                                       acc[mt][nt][half * 2 + 1]);
                *(float2*)op = w;
            }
        }
    }
}

// ---------------------------------------------------------------------------
// Kernel 3: fused vector-hull with ballot-gated saturation fast-path
// ---------------------------------------------------------------------------
#define TOKS_PER_WARP 4
#define SAT_T 16.0f

__global__ __launch_bounds__(256)
void vhull_kernel(const float* __restrict__ x,
                  const float* __restrict__ b1,
                  const float* __restrict__ b2,
                  const float* __restrict__ gate_w,
                  const float* __restrict__ gate_b,
                  float* __restrict__ vout) {
    __shared__ float sW1[PP * DD];
    __shared__ float sB1[PP * DD];
    __shared__ float sW2[PP * DD];
    __shared__ float sB2[PP * DD];
    __shared__ float sGw[DD];

    int h = blockIdx.y;
    for (int i = threadIdx.x; i < PP * DD; i += 256) {
        sW1[i] = g_Wsum1[h * PP * DD + i];
        sB1[i] = b1[h * PP * DD + i];
        sW2[i] = g_Wsum2[h * PP * DD + i];
        sB2[i] = b2[h * PP * DD + i];
    }
    if (threadIdx.x < DD) sGw[threadIdx.x] = gate_w[h * DD + threadIdx.x];
    float gb = gate_b[h];
    __syncthreads();

    int warp = threadIdx.x >> 5;
    int lane = threadIdx.x & 31;
    int tokBase = (blockIdx.x * 8 + warp) * TOKS_PER_WARP;

    for (int t = 0; t < TOKS_PER_WARP; ++t) {
        int n = tokBase + t;
        const float* xp = x + (size_t)n * EE + h * DD;
        float xh0 = xp[lane];
        float xh1 = xp[lane + 32];

        float dot = warp_sum(xh0 * sGw[lane] + xh1 * sGw[lane + 32]);
        float u = sqspf(dot + gb);
        float g = 1.0f - __expf(-u);
        float xg0 = xh0 * g;
        float xg1 = xh1 * g;

        float s  = warp_sum(xg0 + xg1);
        float q2 = warp_sum(xg0 * xg0 + xg1 * xg1);
        float tau = sqrtf(q2 * (1.0f / DD) + C_EPS + C_NU);
        float inv_tau = 1.0f / tau;

        // layer 1: t[p] = sum_o sqsp(s*W1sum[p,o] + b1[p,o])
        float tp[PP];
#pragma unroll
        for (int p = 0; p < PP; ++p) {
            int i0 = p * DD + lane;
            float z0 = fmaf(s, sW1[i0],      sB1[i0]);
            float z1 = fmaf(s, sW1[i0 + 32], sB1[i0 + 32]);
            bool need = (fabsf(z0) < SAT_T) || (fabsf(z1) < SAT_T);
            float y0, y1;
            if (__ballot_sync(0xffffffffu, need)) {
                y0 = sqspf(z0);
                y1 = sqspf(z1);
            } else {
                y0 = sqsp_cheap(z0);
                y1 = sqsp_cheap(z1);
            }
            tp[p] = warp_sum(y0 + y1);
        }

        // layer 2 + logsumexp over p
        float vres[2];
#pragma unroll
        for (int oo = 0; oo < 2; ++oo) {
            int o = lane + oo * 32;
            float a[PP];
            float m = -3.4e38f;
#pragma unroll
            for (int p = 0; p < PP; ++p) {
                float z = fmaf(tp[p], sW2[p * DD + o], sB2[p * DD + o]);
                bool need = fabsf(z) < SAT_T;
                float av;
                if (__ballot_sync(0xffffffffu, need)) av = sqspf(z);
                else                                  av = sqsp_cheap(z);
                a[p] = av;
                m = fmaxf(m, av);
            }
            float sume = 0.0f;
#pragma unroll
            for (int p = 0; p < PP; ++p)
                sume += __expf((a[p] - m) * tau);
            vres[oo] = m + __logf(sume) * inv_tau;
        }

        int b_ = n >> 11;
        int s_ = n & (SS - 1);
        float* op = vout + (((size_t)b_ * HH + h) * SS + s_) * DD;
        op[lane]      = vres[0];
        op[lane + 32] = vres[1];
    }
}

// ---------------------------------------------------------------------------
// launch
// ---------------------------------------------------------------------------
extern "C" void kernel_launch(void* const* d_in, const int* in_sizes, int n_in,
                              void* d_out, int out_size) {
    const float* x      = (const float*)d_in[0];
    const float* qk_w   = (const float*)d_in[1];
    const float* W1     = (const float*)d_in[2];
    const float* b1     = (const float*)d_in[3];
    const float* W2     = (const float*)d_in[4];
    const float* b2     = (const float*)d_in[5];
    const float* gate_w = (const float*)d_in[6];
    const float* gate_b = (const float*)d_in[7];
    float* out = (float*)d_out;

    __half *xhi_p, *xlo_p, *whi_p;
    cudaGetSymbolAddress((void**)&xhi_p, g_xhi);
    cudaGetSymbolAddress((void**)&xlo_p, g_xlo);
    cudaGetSymbolAddress((void**)&whi_p, g_whi);

    {
        int n4 = NTOK * EE / 4;
        cvt_split_kernel<<<(n4 + 255) / 256, 256>>>((const float4*)x,
                                                    (uint2*)xhi_p, (uint2*)xlo_p, n4);
        int m4 = NQK * EE / 4;
        cvt_hi_kernel<<<(m4 + 255) / 256, 256>>>((const float4*)qk_w,
                                                 (uint2*)whi_p, m4);
    }

    wsum_kernel<<<1024, 256>>>(W1, W2);

    cudaFuncSetAttribute(qk_gemm_mma,
                         cudaFuncAttributeMaxDynamicSharedMemorySize, SMEMB);
    dim3 ggrid(NQK / BN, NTOK / BM);   // (16, 64) = 1024 CTAs
    qk_gemm_mma<<<ggrid, 256, SMEMB>>>(out);

    dim3 vgrid(NTOK / (8 * TOKS_PER_WARP), HH);
    vhull_kernel<<<vgrid, 256>>>(x, b1, b2, gate_w, gate_b,
                                 out + 2 * (size_t)QSIZE);
}

// round 13
// speedup vs baseline: 4.1640x; 1.4012x over previous
// R13: third submission of the R11 content (broker failed 2x twice more;
// never ran on HW — R8/R9/R10 precedent: identical source passed on retry 3).
// Plain fp16 GEMM (A-lo dropped; combined rounding ~2.9e-4 < 1e-3), KC=64.
#include <cuda_runtime.h>
#include <cuda_fp16.h>
#include <cstdint>

#define BB 4
#define SS 2048
#define EE 1024
#define HH 16
#define PP 8
#define DD 64
#define NTOK (BB*SS)          // 8192
#define QSIZE (BB*HH*SS*DD)   // 8,388,608 floats per tensor
#define NQK 2048

#define C_B 2.0480546988460353f
#define C_C 0.841470984807896f
#define C_A 0.45339765151640377f
#define C_NU 0.999999327348f
#define C_EPS 1e-6f

// ---------------------------------------------------------------------------
// Scratch
// ---------------------------------------------------------------------------
__device__ float g_Wsum1[HH*PP*DD];
__device__ float g_Wsum2[HH*PP*DD];
__device__ __half g_xhi[(size_t)NTOK*EE];
__device__ __half g_whi[(size_t)NQK*EE];

// ---------------------------------------------------------------------------
// helpers
// ---------------------------------------------------------------------------
__device__ __forceinline__ uint32_t smem_u32(const void* p) {
    uint32_t a;
    asm("{ .reg .u64 t; cvta.to.shared.u64 t, %1; cvt.u32.u64 %0, t; }"
        : "=r"(a) : "l"(p));
    return a;
}
__device__ __forceinline__ float warp_sum(float v) {
#pragma unroll
    for (int o = 16; o; o >>= 1) v += __shfl_xor_sync(0xffffffffu, v, o);
    return v;
}
__device__ __forceinline__ float softplusf(float z) {
    float az = fabsf(z);
    float e  = __expf(-az);
    return fmaxf(z, 0.0f) + __logf(1.0f + e);
}
__device__ __forceinline__ float sqspf(float x) {
    float t1 = softplusf(C_B * x) * (1.0f / C_B);
    float t2 = softplusf(C_C * x) * (1.0f / C_C);
    float y  = (1.0f - C_A) * t1 + C_A * t2;
    return y * y;
}
// saturated sqsp: exact for |z| >= 16 (softplus error < 2e-7 there)
__device__ __forceinline__ float sqsp_cheap(float z) {
    float p = fmaxf(z, 0.0f);
    return p * p;
}

__device__ __forceinline__ void cp16(uint32_t d, const void* s) {
    asm volatile("cp.async.cg.shared.global [%0], [%1], 16;"
                 :: "r"(d), "l"(__cvta_generic_to_global(s)) : "memory");
}
__device__ __forceinline__ void cp_commit() {
    asm volatile("cp.async.commit_group;" ::: "memory");
}
template<int N> __device__ __forceinline__ void cp_wait() {
    asm volatile("cp.async.wait_group %0;" :: "n"(N) : "memory");
}
__device__ __forceinline__ void ldsm4(uint32_t* r, uint32_t a) {
    asm volatile("ldmatrix.sync.aligned.m8n8.x4.shared.b16 {%0,%1,%2,%3}, [%4];"
                 : "=r"(r[0]), "=r"(r[1]), "=r"(r[2]), "=r"(r[3]) : "r"(a));
}
__device__ __forceinline__ void mma16816(float* d, const uint32_t* a,
                                         const uint32_t* b) {
    asm volatile(
        "mma.sync.aligned.m16n8k16.row.col.f32.f16.f16.f32 "
        "{%0,%1,%2,%3}, {%4,%5,%6,%7}, {%8,%9}, {%0,%1,%2,%3};"
        : "+f"(d[0]), "+f"(d[1]), "+f"(d[2]), "+f"(d[3])
        : "r"(a[0]), "r"(a[1]), "r"(a[2]), "r"(a[3]), "r"(b[0]), "r"(b[1]));
}

// ---------------------------------------------------------------------------
// Kernel 0: fp32 -> fp16 (round-to-nearest)
// ---------------------------------------------------------------------------
__global__ void cvt_hi_kernel(const float4* __restrict__ src,
                              uint2* __restrict__ hi, int n4) {
    int i = blockIdx.x * blockDim.x + threadIdx.x;
    if (i >= n4) return;
    float4 v = src[i];
    __half2 h01 = __float22half2_rn(make_float2(v.x, v.y));
    __half2 h23 = __float22half2_rn(make_float2(v.z, v.w));
    hi[i] = make_uint2(*reinterpret_cast<uint32_t*>(&h01),
                       *reinterpret_cast<uint32_t*>(&h23));
}

// ---------------------------------------------------------------------------
// Kernel 1: Wsum[h,p,o] = sum_j W[h,p,o,j]
// ---------------------------------------------------------------------------
__global__ void wsum_kernel(const float* __restrict__ W1,
                            const float* __restrict__ W2) {
    int idx  = blockIdx.x * 8 + (threadIdx.x >> 5);
    int lane = threadIdx.x & 31;
    const float* w1 = W1 + (size_t)idx * DD;
    const float* w2 = W2 + (size_t)idx * DD;
    float s1 = warp_sum(w1[lane] + w1[lane + 32]);
    float s2 = warp_sum(w2[lane] + w2[lane + 32]);
    if (lane == 0) { g_Wsum1[idx] = s1; g_Wsum2[idx] = s2; }
}

// ---------------------------------------------------------------------------
// Kernel 2: plain fp16 GEMM, tile 128x128, KC=64, warp tile 32x64,
// 3-stage cp.async pipeline (16 chunks, 16 barriers).
// ---------------------------------------------------------------------------
#define BM 128
#define BN 128
#define KC 64
#define RS 144                     // 128 B data + 16 pad
#define SA 0
#define SB (BM*RS)                 // 18432
#define STAGE (2*BM*RS)            // 36864
#define NSTAGE 3
#define SMEMB (NSTAGE*STAGE)       // 110592
#define NCH (EE/KC)                // 16

__device__ __forceinline__ void prefetch(uint32_t sbase, int stage,
                                         int tileM, int tileN, int c, int tid) {
    uint32_t st = sbase + (uint32_t)stage * STAGE;
    int kb = c * KC;
#pragma unroll
    for (int i = 0; i < 4; ++i) {
        int idx = tid + i * 256;
        int row = idx >> 3, co = idx & 7;         // 128 rows x 8 x 16B
        uint32_t soff = (uint32_t)(row * RS + co * 16);
        size_t ga = (size_t)(tileM * BM + row) * EE + kb + co * 8;
        size_t gb = (size_t)(tileN * BN + row) * EE + kb + co * 8;
        cp16(st + SA + soff, g_xhi + ga);
        cp16(st + SB + soff, g_whi + gb);
    }
}

__global__ __launch_bounds__(256, 2)
void qk_gemm_mma(float* __restrict__ out) {
    extern __shared__ char dsm[];
    uint32_t sbase = smem_u32(dsm);
    int tid = threadIdx.x, wid = tid >> 5, lane = tid & 31;
    int tileN = blockIdx.x, tileM = blockIdx.y;

    float acc[2][8][4];
#pragma unroll
    for (int a = 0; a < 2; ++a)
#pragma unroll
        for (int b = 0; b < 8; ++b)
#pragma unroll
            for (int cc = 0; cc < 4; ++cc) acc[a][b][cc] = 0.0f;

    prefetch(sbase, 0, tileM, tileN, 0, tid);
    cp_commit();
    prefetch(sbase, 1, tileM, tileN, 1, tid);
    cp_commit();

    int wm = (wid & 3) * 32;   // 4 warps across M
    int wn = (wid >> 2) * 64;  // 2 warps across N
    int r8 = lane & 7, sub = lane >> 3;

    int stage = 0;
    for (int c = 0; c < NCH; ++c) {
        cp_wait<1>();            // chunk c resident
        __syncthreads();
        if (c + 2 < NCH)
            prefetch(sbase, (stage + 2) % NSTAGE, tileM, tileN, c + 2, tid);
        cp_commit();             // always commit (keeps group count exact)

        uint32_t st = sbase + (uint32_t)stage * STAGE;
#pragma unroll
        for (int kk = 0; kk < 4; ++kk) {   // four k16 steps per KC=64
            uint32_t ah[2][4], bh[8][2];
#pragma unroll
            for (int mt = 0; mt < 2; ++mt) {
                uint32_t ra = st + SA +
                    (uint32_t)((wm + mt * 16 + r8 + (sub & 1) * 8) * RS +
                               kk * 32 + (sub >> 1) * 16);
                ldsm4(ah[mt], ra);
            }
#pragma unroll
            for (int p = 0; p < 4; ++p) {
                uint32_t rb = st + SB +
                    (uint32_t)((wn + p * 16 + r8 + (sub >> 1) * 8) * RS +
                               kk * 32 + (sub & 1) * 16);
                uint32_t t4[4];
                ldsm4(t4, rb);
                bh[2 * p][0] = t4[0]; bh[2 * p][1] = t4[1];
                bh[2 * p + 1][0] = t4[2]; bh[2 * p + 1][1] = t4[3];
            }
#pragma unroll
            for (int mt = 0; mt < 2; ++mt)
#pragma unroll
                for (int nt = 0; nt < 8; ++nt)
                    mma16816(acc[mt][nt], ah[mt], bh[nt]);
        }
        stage = (stage + 1) % NSTAGE;
    }

    // epilogue -> q/k (B,H,S,D) scatter
    int g = lane >> 2, t2 = (lane & 3) * 2;
#pragma unroll
    for (int mt = 0; mt < 2; ++mt) {
        int mrow0 = tileM * BM + wm + mt * 16 + g;
#pragma unroll
        for (int half = 0; half < 2; ++half) {
            int m = mrow0 + half * 8;
            int b_ = m >> 11;
            int s_ = m & (SS - 1);
#pragma unroll
            for (int nt = 0; nt < 8; ++nt) {
                int j = tileN * BN + wn + nt * 8 + t2;
                size_t toff = (j >= EE) ? (size_t)QSIZE : 0;
                int jc = j & (EE - 1);
                int h  = jc >> 6;
                int d0 = jc & 63;
                float* op = out + toff +
                            (((size_t)b_ * HH + h) * SS + s_) * DD + d0;
                float2 w = make_float2(acc[mt][nt][half * 2 + 0],
                                       acc[mt][nt][half * 2 + 1]);
                *(float2*)op = w;
            }
        }
    }
}

// ---------------------------------------------------------------------------
// Kernel 3: fused vector-hull with ballot-gated saturation fast-path
// ---------------------------------------------------------------------------
#define TOKS_PER_WARP 4
#define SAT_T 16.0f

__global__ __launch_bounds__(256)
void vhull_kernel(const float* __restrict__ x,
                  const float* __restrict__ b1,
                  const float* __restrict__ b2,
                  const float* __restrict__ gate_w,
                  const float* __restrict__ gate_b,
                  float* __restrict__ vout) {
    __shared__ float sW1[PP * DD];
    __shared__ float sB1[PP * DD];
    __shared__ float sW2[PP * DD];
    __shared__ float sB2[PP * DD];
    __shared__ float sGw[DD];

    int h = blockIdx.y;
    for (int i = threadIdx.x; i < PP * DD; i += 256) {
        sW1[i] = g_Wsum1[h * PP * DD + i];
        sB1[i] = b1[h * PP * DD + i];
        sW2[i] = g_Wsum2[h * PP * DD + i];
        sB2[i] = b2[h * PP * DD + i];
    }
    if (threadIdx.x < DD) sGw[threadIdx.x] = gate_w[h * DD + threadIdx.x];
    float gb = gate_b[h];
    __syncthreads();

    int warp = threadIdx.x >> 5;
    int lane = threadIdx.x & 31;
    int tokBase = (blockIdx.x * 8 + warp) * TOKS_PER_WARP;

    for (int t = 0; t < TOKS_PER_WARP; ++t) {
        int n = tokBase + t;
        const float* xp = x + (size_t)n * EE + h * DD;
        float xh0 = xp[lane];
        float xh1 = xp[lane + 32];

        float dot = warp_sum(xh0 * sGw[lane] + xh1 * sGw[lane + 32]);
        float u = sqspf(dot + gb);
        float g = 1.0f - __expf(-u);
        float xg0 = xh0 * g;
        float xg1 = xh1 * g;

        float s  = warp_sum(xg0 + xg1);
        float q2 = warp_sum(xg0 * xg0 + xg1 * xg1);
        float tau = sqrtf(q2 * (1.0f / DD) + C_EPS + C_NU);
        float inv_tau = 1.0f / tau;

        // layer 1: t[p] = sum_o sqsp(s*W1sum[p,o] + b1[p,o])
        float tp[PP];
#pragma unroll
        for (int p = 0; p < PP; ++p) {
            int i0 = p * DD + lane;
            float z0 = fmaf(s, sW1[i0],      sB1[i0]);
            float z1 = fmaf(s, sW1[i0 + 32], sB1[i0 + 32]);
            bool need = (fabsf(z0) < SAT_T) || (fabsf(z1) < SAT_T);
            float y0, y1;
            if (__ballot_sync(0xffffffffu, need)) {
                y0 = sqspf(z0);
                y1 = sqspf(z1);
            } else {
                y0 = sqsp_cheap(z0);
                y1 = sqsp_cheap(z1);
            }
            tp[p] = warp_sum(y0 + y1);
        }

        // layer 2 + logsumexp over p
        float vres[2];
#pragma unroll
        for (int oo = 0; oo < 2; ++oo) {
            int o = lane + oo * 32;
            float a[PP];
            float m = -3.4e38f;
#pragma unroll
            for (int p = 0; p < PP; ++p) {
                float z = fmaf(tp[p], sW2[p * DD + o], sB2[p * DD + o]);
                bool need = fabsf(z) < SAT_T;
                float av;
                if (__ballot_sync(0xffffffffu, need)) av = sqspf(z);
                else                                  av = sqsp_cheap(z);
                a[p] = av;
                m = fmaxf(m, av);
            }
            float sume = 0.0f;
#pragma unroll
            for (int p = 0; p < PP; ++p)
                sume += __expf((a[p] - m) * tau);
            vres[oo] = m + __logf(sume) * inv_tau;
        }

        int b_ = n >> 11;
        int s_ = n & (SS - 1);
        float* op = vout + (((size_t)b_ * HH + h) * SS + s_) * DD;
        op[lane]      = vres[0];
        op[lane + 32] = vres[1];
    }
}

// ---------------------------------------------------------------------------
// launch
// ---------------------------------------------------------------------------
extern "C" void kernel_launch(void* const* d_in, const int* in_sizes, int n_in,
                              void* d_out, int out_size) {
    const float* x      = (const float*)d_in[0];
    const float* qk_w   = (const float*)d_in[1];
    const float* W1     = (const float*)d_in[2];
    const float* b1     = (const float*)d_in[3];
    const float* W2     = (const float*)d_in[4];
    const float* b2     = (const float*)d_in[5];
    const float* gate_w = (const float*)d_in[6];
    const float* gate_b = (const float*)d_in[7];
    float* out = (float*)d_out;

    __half *xhi_p, *whi_p;
    cudaGetSymbolAddress((void**)&xhi_p, g_xhi);
    cudaGetSymbolAddress((void**)&whi_p, g_whi);

    {
        int n4 = NTOK * EE / 4;
        cvt_hi_kernel<<<(n4 + 255) / 256, 256>>>((const float4*)x,
                                                 (uint2*)xhi_p, n4);
        int m4 = NQK * EE / 4;
        cvt_hi_kernel<<<(m4 + 255) / 256, 256>>>((const float4*)qk_w,
                                                 (uint2*)whi_p, m4);
    }

    wsum_kernel<<<1024, 256>>>(W1, W2);

    cudaFuncSetAttribute(qk_gemm_mma,
                         cudaFuncAttributeMaxDynamicSharedMemorySize, SMEMB);
    dim3 ggrid(NQK / BN, NTOK / BM);   // (16, 64) = 1024 CTAs
    qk_gemm_mma<<<ggrid, 256, SMEMB>>>(out);

    dim3 vgrid(NTOK / (8 * TOKS_PER_WARP), HH);
    vhull_kernel<<<vgrid, 256>>>(x, b1, b2, gate_w, gate_b,
                                 out + 2 * (size_t)QSIZE);
}

// round 14
// speedup vs baseline: 4.6399x; 1.1143x over previous
// R14: vhull fast paths — runtime-verified algebraic layer-1 (per-head
// moments+threshold from hconst_kernel), z==0 -> sqsp(0) constant, uniform
// logsumexp shortcut. GEMM/cvt/wsum identical to R13 winner.
#include <cuda_runtime.h>
#include <cuda_fp16.h>
#include <cstdint>

#define BB 4
#define SS 2048
#define EE 1024
#define HH 16
#define PP 8
#define DD 64
#define NTOK (BB*SS)          // 8192
#define QSIZE (BB*HH*SS*DD)   // 8,388,608 floats per tensor
#define NQK 2048

#define C_B 2.0480546988460353f
#define C_C 0.841470984807896f
#define C_A 0.45339765151640377f
#define C_NU 0.999999327348f
#define C_EPS 1e-6f
#define SAT_T 16.0f
#define SQSP0F 0.3118852f      // sqsp(0) = (ln2*((1-A)/B + A/C))^2
#define LOG8F 2.0794415417f    // ln(8)

// ---------------------------------------------------------------------------
// Scratch
// ---------------------------------------------------------------------------
__device__ float g_Wsum1[HH*PP*DD];
__device__ float g_Wsum2[HH*PP*DD];
__device__ float g_SW2[HH*PP];     // sum_o Wsum1^2
__device__ float g_SWB[HH*PP];     // sum_o Wsum1*b1
__device__ float g_SB2m[HH*PP];    // sum_o b1^2
__device__ float g_thr1[HH];       // saturation threshold (FLT_MAX = disabled)
__device__ __half g_xhi[(size_t)NTOK*EE];
__device__ __half g_whi[(size_t)NQK*EE];

// ---------------------------------------------------------------------------
// helpers
// ---------------------------------------------------------------------------
__device__ __forceinline__ uint32_t smem_u32(const void* p) {
    uint32_t a;
    asm("{ .reg .u64 t; cvta.to.shared.u64 t, %1; cvt.u32.u64 %0, t; }"
        : "=r"(a) : "l"(p));
    return a;
}
__device__ __forceinline__ float warp_sum(float v) {
#pragma unroll
    for (int o = 16; o; o >>= 1) v += __shfl_xor_sync(0xffffffffu, v, o);
    return v;
}
__device__ __forceinline__ float softplusf(float z) {
    float az = fabsf(z);
    float e  = __expf(-az);
    return fmaxf(z, 0.0f) + __logf(1.0f + e);
}
__device__ __forceinline__ float sqspf(float x) {
    float t1 = softplusf(C_B * x) * (1.0f / C_B);
    float t2 = softplusf(C_C * x) * (1.0f / C_C);
    float y  = (1.0f - C_A) * t1 + C_A * t2;
    return y * y;
}
__device__ __forceinline__ float sqsp_cheap(float z) {
    float p = fmaxf(z, 0.0f);
    return p * p;
}

__device__ __forceinline__ void cp16(uint32_t d, const void* s) {
    asm volatile("cp.async.cg.shared.global [%0], [%1], 16;"
                 :: "r"(d), "l"(__cvta_generic_to_global(s)) : "memory");
}
__device__ __forceinline__ void cp_commit() {
    asm volatile("cp.async.commit_group;" ::: "memory");
}
template<int N> __device__ __forceinline__ void cp_wait() {
    asm volatile("cp.async.wait_group %0;" :: "n"(N) : "memory");
}
__device__ __forceinline__ void ldsm4(uint32_t* r, uint32_t a) {
    asm volatile("ldmatrix.sync.aligned.m8n8.x4.shared.b16 {%0,%1,%2,%3}, [%4];"
                 : "=r"(r[0]), "=r"(r[1]), "=r"(r[2]), "=r"(r[3]) : "r"(a));
}
__device__ __forceinline__ void mma16816(float* d, const uint32_t* a,
                                         const uint32_t* b) {
    asm volatile(
        "mma.sync.aligned.m16n8k16.row.col.f32.f16.f16.f32 "
        "{%0,%1,%2,%3}, {%4,%5,%6,%7}, {%8,%9}, {%0,%1,%2,%3};"
        : "+f"(d[0]), "+f"(d[1]), "+f"(d[2]), "+f"(d[3])
        : "r"(a[0]), "r"(a[1]), "r"(a[2]), "r"(a[3]), "r"(b[0]), "r"(b[1]));
}

// ---------------------------------------------------------------------------
// Kernel 0: fp32 -> fp16 (round-to-nearest)
// ---------------------------------------------------------------------------
__global__ void cvt_hi_kernel(const float4* __restrict__ src,
                              uint2* __restrict__ hi, int n4) {
    int i = blockIdx.x * blockDim.x + threadIdx.x;
    if (i >= n4) return;
    float4 v = src[i];
    __half2 h01 = __float22half2_rn(make_float2(v.x, v.y));
    __half2 h23 = __float22half2_rn(make_float2(v.z, v.w));
    hi[i] = make_uint2(*reinterpret_cast<uint32_t*>(&h01),
                       *reinterpret_cast<uint32_t*>(&h23));
}

// ---------------------------------------------------------------------------
// Kernel 1: Wsum[h,p,o] = sum_j W[h,p,o,j]
// ---------------------------------------------------------------------------
__global__ void wsum_kernel(const float* __restrict__ W1,
                            const float* __restrict__ W2) {
    int idx  = blockIdx.x * 8 + (threadIdx.x >> 5);
    int lane = threadIdx.x & 31;
    const float* w1 = W1 + (size_t)idx * DD;
    const float* w2 = W2 + (size_t)idx * DD;
    float s1 = warp_sum(w1[lane] + w1[lane + 32]);
    float s2 = warp_sum(w2[lane] + w2[lane + 32]);
    if (lane == 0) { g_Wsum1[idx] = s1; g_Wsum2[idx] = s2; }
}

// ---------------------------------------------------------------------------
// Kernel 1b: per-head moments + saturation threshold (runtime-verified)
// ---------------------------------------------------------------------------
__global__ void hconst_kernel(const float* __restrict__ b1) {
    __shared__ float s_sw2[PP], s_swb[PP], s_sb2[PP];
    __shared__ float s_mw[8], s_mb[8];
    int h = blockIdx.x;
    int tid = threadIdx.x;
    if (tid < PP) { s_sw2[tid] = 0.f; s_swb[tid] = 0.f; s_sb2[tid] = 0.f; }
    __syncthreads();
    float lmaxW = -3.4e38f, lbmax = 0.f;
    for (int i = tid; i < PP * DD; i += 256) {
        float w = g_Wsum1[h * PP * DD + i];
        float b = b1[h * PP * DD + i];
        int p = i >> 6;
        atomicAdd(&s_sw2[p], w * w);
        atomicAdd(&s_swb[p], w * b);
        atomicAdd(&s_sb2[p], b * b);
        lmaxW = fmaxf(lmaxW, w);
        lbmax = fmaxf(lbmax, fabsf(b));
    }
#pragma unroll
    for (int o = 16; o; o >>= 1) {
        lmaxW = fmaxf(lmaxW, __shfl_xor_sync(0xffffffffu, lmaxW, o));
        lbmax = fmaxf(lbmax, __shfl_xor_sync(0xffffffffu, lbmax, o));
    }
    if ((tid & 31) == 0) { s_mw[tid >> 5] = lmaxW; s_mb[tid >> 5] = lbmax; }
    __syncthreads();
    if (tid == 0) {
        float mW = s_mw[0], mB = s_mb[0];
        for (int i = 1; i < 8; ++i) {
            mW = fmaxf(mW, s_mw[i]);
            mB = fmaxf(mB, s_mb[i]);
        }
        // all Wsum1 < 0 -> |s| >= thr guarantees every |z| >= SAT_T
        g_thr1[h] = (mW < 0.0f) ? (SAT_T + mB) / (-mW) : 3.4e38f;
    }
    if (tid < PP) {
        g_SW2[h * PP + tid]  = s_sw2[tid];
        g_SWB[h * PP + tid]  = s_swb[tid];
        g_SB2m[h * PP + tid] = s_sb2[tid];
    }
}

// ---------------------------------------------------------------------------
// Kernel 2: plain fp16 GEMM, tile 128x128, KC=64, warp tile 32x64,
// 3-stage cp.async pipeline (identical to R13)
// ---------------------------------------------------------------------------
#define BM 128
#define BN 128
#define KC 64
#define RS 144
#define SA 0
#define SB (BM*RS)
#define STAGE (2*BM*RS)
#define NSTAGE 3
#define SMEMB (NSTAGE*STAGE)
#define NCH (EE/KC)

__device__ __forceinline__ void prefetch(uint32_t sbase, int stage,
                                         int tileM, int tileN, int c, int tid) {
    uint32_t st = sbase + (uint32_t)stage * STAGE;
    int kb = c * KC;
#pragma unroll
    for (int i = 0; i < 4; ++i) {
        int idx = tid + i * 256;
        int row = idx >> 3, co = idx & 7;
        uint32_t soff = (uint32_t)(row * RS + co * 16);
        size_t ga = (size_t)(tileM * BM + row) * EE + kb + co * 8;
        size_t gb = (size_t)(tileN * BN + row) * EE + kb + co * 8;
        cp16(st + SA + soff, g_xhi + ga);
        cp16(st + SB + soff, g_whi + gb);
    }
}

__global__ __launch_bounds__(256, 2)
void qk_gemm_mma(float* __restrict__ out) {
    extern __shared__ char dsm[];
    uint32_t sbase = smem_u32(dsm);
    int tid = threadIdx.x, wid = tid >> 5, lane = tid & 31;
    int tileN = blockIdx.x, tileM = blockIdx.y;

    float acc[2][8][4];
#pragma unroll
    for (int a = 0; a < 2; ++a)
#pragma unroll
        for (int b = 0; b < 8; ++b)
#pragma unroll
            for (int cc = 0; cc < 4; ++cc) acc[a][b][cc] = 0.0f;

    prefetch(sbase, 0, tileM, tileN, 0, tid);
    cp_commit();
    prefetch(sbase, 1, tileM, tileN, 1, tid);
    cp_commit();

    int wm = (wid & 3) * 32;
    int wn = (wid >> 2) * 64;
    int r8 = lane & 7, sub = lane >> 3;

    int stage = 0;
    for (int c = 0; c < NCH; ++c) {
        cp_wait<1>();
        __syncthreads();
        if (c + 2 < NCH)
            prefetch(sbase, (stage + 2) % NSTAGE, tileM, tileN, c + 2, tid);
        cp_commit();

        uint32_t st = sbase + (uint32_t)stage * STAGE;
#pragma unroll
        for (int kk = 0; kk < 4; ++kk) {
            uint32_t ah[2][4], bh[8][2];
#pragma unroll
            for (int mt = 0; mt < 2; ++mt) {
                uint32_t ra = st + SA +
                    (uint32_t)((wm + mt * 16 + r8 + (sub & 1) * 8) * RS +
                               kk * 32 + (sub >> 1) * 16);
                ldsm4(ah[mt], ra);
            }
#pragma unroll
            for (int p = 0; p < 4; ++p) {
                uint32_t rb = st + SB +
                    (uint32_t)((wn + p * 16 + r8 + (sub >> 1) * 8) * RS +
                               kk * 32 + (sub & 1) * 16);
                uint32_t t4[4];
                ldsm4(t4, rb);
                bh[2 * p][0] = t4[0]; bh[2 * p][1] = t4[1];
                bh[2 * p + 1][0] = t4[2]; bh[2 * p + 1][1] = t4[3];
            }
#pragma unroll
            for (int mt = 0; mt < 2; ++mt)
#pragma unroll
                for (int nt = 0; nt < 8; ++nt)
                    mma16816(acc[mt][nt], ah[mt], bh[nt]);
        }
        stage = (stage + 1) % NSTAGE;
    }

    int g = lane >> 2, t2 = (lane & 3) * 2;
#pragma unroll
    for (int mt = 0; mt < 2; ++mt) {
        int mrow0 = tileM * BM + wm + mt * 16 + g;
#pragma unroll
        for (int half = 0; half < 2; ++half) {
            int m = mrow0 + half * 8;
            int b_ = m >> 11;
            int s_ = m & (SS - 1);
#pragma unroll
            for (int nt = 0; nt < 8; ++nt) {
                int j = tileN * BN + wn + nt * 8 + t2;
                size_t toff = (j >= EE) ? (size_t)QSIZE : 0;
                int jc = j & (EE - 1);
                int h  = jc >> 6;
                int d0 = jc & 63;
                float* op = out + toff +
                            (((size_t)b_ * HH + h) * SS + s_) * DD + d0;
                float2 w = make_float2(acc[mt][nt][half * 2 + 0],
                                       acc[mt][nt][half * 2 + 1]);
                *(float2*)op = w;
            }
        }
    }
}

// ---------------------------------------------------------------------------
// Kernel 3: fused vector-hull with algebraic layer-1 + lse shortcuts
// ---------------------------------------------------------------------------
#define TOKS_PER_WARP 4

__global__ __launch_bounds__(256)
void vhull_kernel(const float* __restrict__ x,
                  const float* __restrict__ b1,
                  const float* __restrict__ b2,
                  const float* __restrict__ gate_w,
                  const float* __restrict__ gate_b,
                  float* __restrict__ vout) {
    __shared__ float sW1[PP * DD];
    __shared__ float sB1[PP * DD];
    __shared__ float sW2[PP * DD];
    __shared__ float sB2[PP * DD];
    __shared__ float sGw[DD];
    __shared__ float sSW2[PP], sSWB[PP], sSB2m[PP];

    int h = blockIdx.y;
    for (int i = threadIdx.x; i < PP * DD; i += 256) {
        sW1[i] = g_Wsum1[h * PP * DD + i];
        sB1[i] = b1[h * PP * DD + i];
        sW2[i] = g_Wsum2[h * PP * DD + i];
        sB2[i] = b2[h * PP * DD + i];
    }
    if (threadIdx.x < DD) sGw[threadIdx.x] = gate_w[h * DD + threadIdx.x];
    if (threadIdx.x < PP) {
        sSW2[threadIdx.x]  = g_SW2[h * PP + threadIdx.x];
        sSWB[threadIdx.x]  = g_SWB[h * PP + threadIdx.x];
        sSB2m[threadIdx.x] = g_SB2m[h * PP + threadIdx.x];
    }
    float gb = gate_b[h];
    float thr1 = g_thr1[h];
    __syncthreads();

    int warp = threadIdx.x >> 5;
    int lane = threadIdx.x & 31;
    int tokBase = (blockIdx.x * 8 + warp) * TOKS_PER_WARP;

    for (int t = 0; t < TOKS_PER_WARP; ++t) {
        int n = tokBase + t;
        const float* xp = x + (size_t)n * EE + h * DD;
        float xh0 = xp[lane];
        float xh1 = xp[lane + 32];

        float dot = warp_sum(xh0 * sGw[lane] + xh1 * sGw[lane + 32]);
        float u = sqspf(dot + gb);
        float g = 1.0f - __expf(-u);
        float xg0 = xh0 * g;
        float xg1 = xh1 * g;

        float s  = warp_sum(xg0 + xg1);
        float q2 = warp_sum(xg0 * xg0 + xg1 * xg1);
        float tau = sqrtf(q2 * (1.0f / DD) + C_EPS + C_NU);
        float inv_tau = 1.0f / tau;

        // layer 1: t[p] = sum_o sqsp(s*W1sum[p,o] + b1[p,o])
        float tp[PP];
        if (s >= thr1) {
            // all z <= -SAT_T -> sqsp ~ 0
#pragma unroll
            for (int p = 0; p < PP; ++p) tp[p] = 0.0f;
        } else if (s <= -thr1) {
            // all z >= SAT_T -> sqsp ~ z^2; sum algebraically from moments
            float s2 = s * s, s2x = 2.0f * s;
#pragma unroll
            for (int p = 0; p < PP; ++p)
                tp[p] = fmaf(s2, sSW2[p], fmaf(s2x, sSWB[p], sSB2m[p]));
        } else {
            // full path (identical to R13)
#pragma unroll
            for (int p = 0; p < PP; ++p) {
                int i0 = p * DD + lane;
                float z0 = fmaf(s, sW1[i0],      sB1[i0]);
                float z1 = fmaf(s, sW1[i0 + 32], sB1[i0 + 32]);
                bool need = (fabsf(z0) < SAT_T) || (fabsf(z1) < SAT_T);
                float y0, y1;
                if (__ballot_sync(0xffffffffu, need)) {
                    y0 = sqspf(z0);
                    y1 = sqspf(z1);
                } else {
                    y0 = sqsp_cheap(z0);
                    y1 = sqsp_cheap(z1);
                }
                tp[p] = warp_sum(y0 + y1);
            }
        }

        // layer 2 + logsumexp over p
        float vres[2];
#pragma unroll
        for (int oo = 0; oo < 2; ++oo) {
            int o = lane + oo * 32;
            float a[PP];
            float m = -3.4e38f, mn = 3.4e38f;
#pragma unroll
            for (int p = 0; p < PP; ++p) {
                float z = fmaf(tp[p], sW2[p * DD + o], sB2[p * DD + o]);
                bool need = (fabsf(z) < SAT_T) && (z != 0.0f);
                float av;
                if (__ballot_sync(0xffffffffu, need)) {
                    av = sqspf(z);               // warp-uniform exact path
                } else {
                    av = (z == 0.0f) ? SQSP0F : sqsp_cheap(z);
                }
                a[p] = av;
                m = fmaxf(m, av);
                mn = fminf(mn, av);
            }
            if (m == mn) {
                vres[oo] = m + LOG8F * inv_tau;  // all equal: lse = m + ln8/tau
            } else {
                float sume = 0.0f;
#pragma unroll
                for (int p = 0; p < PP; ++p)
                    sume += __expf((a[p] - m) * tau);
                vres[oo] = m + __logf(sume) * inv_tau;
            }
        }

        int b_ = n >> 11;
        int s_ = n & (SS - 1);
        float* op = vout + (((size_t)b_ * HH + h) * SS + s_) * DD;
        op[lane]      = vres[0];
        op[lane + 32] = vres[1];
    }
}

// ---------------------------------------------------------------------------
// launch
// ---------------------------------------------------------------------------
extern "C" void kernel_launch(void* const* d_in, const int* in_sizes, int n_in,
                              void* d_out, int out_size) {
    const float* x      = (const float*)d_in[0];
    const float* qk_w   = (const float*)d_in[1];
    const float* W1     = (const float*)d_in[2];
    const float* b1     = (const float*)d_in[3];
    const float* W2     = (const float*)d_in[4];
    const float* b2     = (const float*)d_in[5];
    const float* gate_w = (const float*)d_in[6];
    const float* gate_b = (const float*)d_in[7];
    float* out = (float*)d_out;

    __half *xhi_p, *whi_p;
    cudaGetSymbolAddress((void**)&xhi_p, g_xhi);
    cudaGetSymbolAddress((void**)&whi_p, g_whi);

    {
        int n4 = NTOK * EE / 4;
        cvt_hi_kernel<<<(n4 + 255) / 256, 256>>>((const float4*)x,
                                                 (uint2*)xhi_p, n4);
        int m4 = NQK * EE / 4;
        cvt_hi_kernel<<<(m4 + 255) / 256, 256>>>((const float4*)qk_w,
                                                 (uint2*)whi_p, m4);
    }

    wsum_kernel<<<1024, 256>>>(W1, W2);
    hconst_kernel<<<HH, 256>>>(b1);

    cudaFuncSetAttribute(qk_gemm_mma,
                         cudaFuncAttributeMaxDynamicSharedMemorySize, SMEMB);
    dim3 ggrid(NQK / BN, NTOK / BM);   // (16, 64) = 1024 CTAs
    qk_gemm_mma<<<ggrid, 256, SMEMB>>>(out);

    dim3 vgrid(NTOK / (8 * TOKS_PER_WARP), HH);
    vhull_kernel<<<vgrid, 256>>>(x, b1, b2, gate_w, gate_b,
                                 out + 2 * (size_t)QSIZE);
}